// round 5
// baseline (speedup 1.0000x reference)
#include <cuda_runtime.h>
#include <math.h>

// VectorExpansion: out[l, p, n] = sin(pi*x*(n+1)) / r * fc * norm * x^l
//   x = r/R_CUT, fc = x<1 ? 0.5*(cos(pi*x)+1) : 0, norm = sqrt(2/R_CUT)
// Output: [4, P, 8] f32
//
// R4: attack L1-wavefront bound (74.3% l1tex, only 46.6% DRAM in R3):
//   - positions padded to float4 by a prepass kernel -> 2x LDG.128 gather
//   - cells + structure_offsets staged in shared memory (tiny)

#define R_CUT_INV (1.0f / 5.0f)
#define NORM 0.6324555320336759f   /* sqrt(2/5) */
#define PI_F 3.14159265358979323846f

#define MAX_N 65536   // atoms (problem: 32768)
#define MAX_S 128     // structures (problem: 32)

__device__ float4 g_pos4[MAX_N];   // 1 MB scratch: padded positions

__global__ __launch_bounds__(256)
void pad_positions_kernel(const float* __restrict__ pos, int N)
{
    int i = blockIdx.x * blockDim.x + threadIdx.x;
    if (i < N) {
        g_pos4[i] = make_float4(pos[3 * i + 0], pos[3 * i + 1], pos[3 * i + 2], 0.0f);
    }
}

__global__ __launch_bounds__(256)
void vexp_kernel(const float*  __restrict__ cells,
                 const int*    __restrict__ shifts,
                 const int2*   __restrict__ pairs,
                 const int*    __restrict__ spair,
                 const int*    __restrict__ soff,
                 float*        __restrict__ out,
                 int P, int S)
{
    __shared__ float s_cells[MAX_S * 9];
    __shared__ int   s_soff[MAX_S];

    for (int i = threadIdx.x; i < S * 9; i += blockDim.x)
        s_cells[i] = cells[i];
    for (int i = threadIdx.x; i < S; i += blockDim.x)
        s_soff[i] = soff[i];
    __syncthreads();

    int p = blockIdx.x * blockDim.x + threadIdx.x;
    if (p >= P) return;

    const int sp  = __ldg(&spair[p]);
    const int off = s_soff[sp];
    const int2 pr = __ldg(&pairs[p]);

    const float fsx = (float)shifts[3 * p + 0];
    const float fsy = (float)shifts[3 * p + 1];
    const float fsz = (float)shifts[3 * p + 2];

    const float* c = s_cells + sp * 9;

    const float4 Pi = __ldg(&g_pos4[off + pr.x]);
    const float4 Pj = __ldg(&g_pos4[off + pr.y]);

    float vx = Pj.x - Pi.x + fsx * c[0] + fsy * c[3] + fsz * c[6];
    float vy = Pj.y - Pi.y + fsx * c[1] + fsy * c[4] + fsz * c[7];
    float vz = Pj.z - Pi.z + fsx * c[2] + fsy * c[5] + fsz * c[8];

    float r2 = fmaf(vx, vx, fmaf(vy, vy, fmaf(vz, vz, 1e-12f)));
    float r  = sqrtf(r2);
    float x  = r * R_CUT_INV;

    const size_t stride_l = (size_t)P * 8;  // floats between l-slabs
    float* obase = out + (size_t)p * 8;

    if (x >= 1.0f) {
        // fc == 0 -> all outputs exactly zero.
        float4 z = make_float4(0.f, 0.f, 0.f, 0.f);
        #pragma unroll
        for (int l = 0; l < 4; l++) {
            float4* ol = reinterpret_cast<float4*>(obase + (size_t)l * stride_l);
            ol[0] = z;
            ol[1] = z;
        }
        return;
    }

    float t  = PI_F * x;
    float c1 = __cosf(t);
    float fc = 0.5f * (c1 + 1.0f);

    float b[8];
    if (x < 0.01f) {
        // Small-r stable branch: sin(n*t)/r = (n*pi/R_CUT) * sinc(n*t),
        // t/r == pi/R_CUT exactly -> no sin/r cancellation.
        float scale = fc * NORM * (PI_F * R_CUT_INV);
        #pragma unroll
        for (int n = 1; n <= 8; n++) {
            float u = (float)n * t;
            b[n - 1] = scale * (float)n * (1.0f - u * u * (1.0f / 6.0f));
        }
    } else {
        // Direct __sinf per harmonic: abs err ~4e-7 * pref(<13) -> <1e-5.
        float pref = fc * NORM / r;
        #pragma unroll
        for (int n = 1; n <= 8; n++) {
            b[n - 1] = __sinf((float)n * t) * pref;
        }
    }

    float xl = 1.0f;
    #pragma unroll
    for (int l = 0; l < 4; l++) {
        float4* ol = reinterpret_cast<float4*>(obase + (size_t)l * stride_l);
        ol[0] = make_float4(b[0] * xl, b[1] * xl, b[2] * xl, b[3] * xl);
        ol[1] = make_float4(b[4] * xl, b[5] * xl, b[6] * xl, b[7] * xl);
        xl *= x;
    }
}

extern "C" void kernel_launch(void* const* d_in, const int* in_sizes, int n_in,
                              void* d_out, int out_size)
{
    const float* positions = (const float*)d_in[0];
    const float* cells     = (const float*)d_in[1];
    const int*   shifts    = (const int*)  d_in[3];
    const int2*  pairs     = (const int2*) d_in[5];
    const int*   spair     = (const int*)  d_in[7];
    const int*   soff      = (const int*)  d_in[8];
    float* out = (float*)d_out;

    int N = in_sizes[0] / 3;     // positions [N,3]
    int S = in_sizes[1] / 9;     // cells [S,3,3]
    int P = in_sizes[7];         // structure_pairs [P]

    pad_positions_kernel<<<(N + 255) / 256, 256>>>(positions, N);

    int threads = 256;
    int blocks  = (P + threads - 1) / threads;
    vexp_kernel<<<blocks, threads>>>(cells, shifts, pairs, spair, soff,
                                     out, P, S);
}

// round 8
// speedup vs baseline: 1.1907x; 1.1907x over previous
#include <cuda_runtime.h>
#include <math.h>

// VectorExpansion: out[l, p, n] = sin(pi*x*(n+1)) / r * fc * norm * x^l
//   x = r/R_CUT, fc = x<1 ? 0.5*(cos(pi*x)+1) : 0, norm = sqrt(2/R_CUT)
// Output: [4, P, 8] f32
//
// R5: 2 threads per pair. Store addresses become lane-contiguous ->
// STG.128 wavefronts per warp drop 8->4 (R4 had 32B lane stride: 50%
// utilization per 128B line). Gather lines coalesce across the lane pair,
// so gather wavefront totals are unchanged.

#define R_CUT_INV (1.0f / 5.0f)
#define NORM 0.6324555320336759f   /* sqrt(2/5) */
#define PI_F 3.14159265358979323846f

#define MAX_N 65536   // atoms (problem: 32768)
#define MAX_S 128     // structures (problem: 32)

__device__ float4 g_pos4[MAX_N];   // 1 MB scratch: padded positions

__global__ __launch_bounds__(256)
void pad_positions_kernel(const float* __restrict__ pos, int N)
{
    int i = blockIdx.x * blockDim.x + threadIdx.x;
    if (i < N) {
        g_pos4[i] = make_float4(pos[3 * i + 0], pos[3 * i + 1], pos[3 * i + 2], 0.0f);
    }
}

__global__ __launch_bounds__(256)
void vexp_kernel(const float*  __restrict__ cells,
                 const int*    __restrict__ shifts,
                 const int2*   __restrict__ pairs,
                 const int*    __restrict__ spair,
                 const int*    __restrict__ soff,
                 float*        __restrict__ out,
                 int P, int S)
{
    __shared__ float s_cells[MAX_S * 9];
    __shared__ int   s_soff[MAX_S];

    for (int i = threadIdx.x; i < S * 9; i += blockDim.x)
        s_cells[i] = cells[i];
    for (int i = threadIdx.x; i < S; i += blockDim.x)
        s_soff[i] = soff[i];
    __syncthreads();

    // Two threads per pair: lanes (2k, 2k+1) share pair k's geometry;
    // half=0 handles n=1..4, half=1 handles n=5..8.
    int t    = blockIdx.x * blockDim.x + threadIdx.x;
    int p    = t >> 1;
    int half = t & 1;
    if (p >= P) return;

    const int sp  = __ldg(&spair[p]);
    const int off = s_soff[sp];
    const int2 pr = __ldg(&pairs[p]);

    const float fsx = (float)shifts[3 * p + 0];
    const float fsy = (float)shifts[3 * p + 1];
    const float fsz = (float)shifts[3 * p + 2];

    const float* c = s_cells + sp * 9;

    const float4 Pi = __ldg(&g_pos4[off + pr.x]);
    const float4 Pj = __ldg(&g_pos4[off + pr.y]);

    float vx = Pj.x - Pi.x + fsx * c[0] + fsy * c[3] + fsz * c[6];
    float vy = Pj.y - Pi.y + fsx * c[1] + fsy * c[4] + fsz * c[7];
    float vz = Pj.z - Pi.z + fsx * c[2] + fsy * c[5] + fsz * c[8];

    float r2 = fmaf(vx, vx, fmaf(vy, vy, fmaf(vz, vz, 1e-12f)));
    float r  = sqrtf(r2);
    float x  = r * R_CUT_INV;

    const size_t stride_l = (size_t)P * 8;                 // floats between l-slabs
    float* obase = out + (size_t)p * 8 + half * 4;         // lane-contiguous across warp

    if (x >= 1.0f) {
        // fc == 0 -> all outputs exactly zero.
        float4 z = make_float4(0.f, 0.f, 0.f, 0.f);
        #pragma unroll
        for (int l = 0; l < 4; l++)
            *reinterpret_cast<float4*>(obase + (size_t)l * stride_l) = z;
        return;
    }

    float t1 = PI_F * x;
    float c1 = __cosf(t1);
    float fc = 0.5f * (c1 + 1.0f);

    // This thread's 4 harmonics: n = n0..n0+3
    const int n0 = 1 + half * 4;
    float b[4];
    if (x < 0.01f) {
        // Small-r stable branch: sin(n*t)/r = (n*pi/R_CUT) * sinc(n*t),
        // t/r == pi/R_CUT exactly -> no sin/r cancellation.
        float scale = fc * NORM * (PI_F * R_CUT_INV);
        #pragma unroll
        for (int k = 0; k < 4; k++) {
            float fn = (float)(n0 + k);
            float u  = fn * t1;
            b[k] = scale * fn * (1.0f - u * u * (1.0f / 6.0f));
        }
    } else {
        // Direct __sinf per harmonic: abs err ~4e-7 * pref(<13) -> <1e-5.
        float pref = fc * NORM / r;
        #pragma unroll
        for (int k = 0; k < 4; k++)
            b[k] = __sinf((float)(n0 + k) * t1) * pref;
    }

    float xl = 1.0f;
    #pragma unroll
    for (int l = 0; l < 4; l++) {
        *reinterpret_cast<float4*>(obase + (size_t)l * stride_l) =
            make_float4(b[0] * xl, b[1] * xl, b[2] * xl, b[3] * xl);
        xl *= x;
    }
}

extern "C" void kernel_launch(void* const* d_in, const int* in_sizes, int n_in,
                              void* d_out, int out_size)
{
    const float* positions = (const float*)d_in[0];
    const float* cells     = (const float*)d_in[1];
    const int*   shifts    = (const int*)  d_in[3];
    const int2*  pairs     = (const int2*) d_in[5];
    const int*   spair     = (const int*)  d_in[7];
    const int*   soff      = (const int*)  d_in[8];
    float* out = (float*)d_out;

    int N = in_sizes[0] / 3;     // positions [N,3]
    int S = in_sizes[1] / 9;     // cells [S,3,3]
    int P = in_sizes[7];         // structure_pairs [P]

    pad_positions_kernel<<<(N + 255) / 256, 256>>>(positions, N);

    int threads = 256;
    long long total = 2LL * P;   // 2 threads per pair
    int blocks = (int)((total + threads - 1) / threads);
    vexp_kernel<<<blocks, threads>>>(cells, shifts, pairs, spair, soff,
                                     out, P, S);
}